// round 16
// baseline (speedup 1.0000x reference)
#include <cuda_runtime.h>
#include <cuda_fp16.h>
#include <cstdint>

#define CC   64
#define TRB  128          // rows per block in pass1
#define MAXN 800000
#define MAXB 8

__device__ float g_scratch[(size_t)MAXN * CC];        // y' = x @ W1a^T
__device__ __align__(16) unsigned char g_w[16384];    // [wh|wh] fp16, pre-swizzled, 64 rows x 256B
__device__ float g_ssx[MAXB * CC];
__device__ float g_ssy[MAXB * CC];
__device__ float g_ssq[CC];
__device__ float g_a[CC];
__device__ float g_d[MAXB * CC];

// ---------------------------------------------------------------------------
__device__ __forceinline__ uint32_t h2_as_u32(__half2 h) {
    return *(uint32_t*)&h;
}

__device__ __forceinline__ void load_bounds(const void* o, int B, int ob[MAXB]) {
    bool i64 = (((const int*)o)[1] == 0);
#pragma unroll
    for (int j = 0; j < MAXB; j++) {
        if (j < B) {
            long long v = i64 ? ((const long long*)o)[j] : (long long)((const int*)o)[j];
            ob[j] = (int)v;
        } else {
            ob[j] = 0x7fffffff;
        }
    }
}
__device__ __forceinline__ int seg_of(int row, const int ob[MAXB]) {
    int s = 0;
#pragma unroll
    for (int j = 0; j < MAXB; j++) s += (row >= ob[j]) ? 1 : 0;
    return s;
}

__device__ __forceinline__ void mma_f16(float* c, uint32_t a0, uint32_t a1,
                                        uint32_t a2, uint32_t a3,
                                        uint32_t b0, uint32_t b1) {
    asm("mma.sync.aligned.m16n8k16.row.col.f32.f16.f16.f32 "
        "{%0,%1,%2,%3}, {%4,%5,%6,%7}, {%8,%9}, {%0,%1,%2,%3};"
        : "+f"(c[0]), "+f"(c[1]), "+f"(c[2]), "+f"(c[3])
        : "r"(a0), "r"(a1), "r"(a2), "r"(a3), "r"(b0), "r"(b1));
}

// ---------------------------------------------------------------------------
// prep: W1a -> fp16, duplicated into both K-halves, swizzled; zero stats.
// Row n = 256B = 64 fp16-pairs; pair p stored at p ^ ((n&7)<<2).
// ---------------------------------------------------------------------------
__global__ void k_prep(const float* __restrict__ w1) {
    int t = blockIdx.x * blockDim.x + threadIdx.x;   // 0..4095
    int n = t >> 6, k = t & 63;
    __half wh = __float2half_rn(w1[n * 2 * CC + k]);
    int p = k >> 1;
    int sw = (n & 7) << 2;
    int pp0 = p ^ sw;            // K-half 1 (pairs 0..31)
    int pp1 = (p + 32) ^ sw;     // K-half 2 (pairs 32..63), same values
    *(__half*)(g_w + n * 256 + pp0 * 4 + (k & 1) * 2) = wh;
    *(__half*)(g_w + n * 256 + pp1 * 4 + (k & 1) * 2) = wh;
    if (t < MAXB * CC) { g_ssx[t] = 0.f; g_ssy[t] = 0.f; }
    if (t < CC) g_ssq[t] = 0.f;
}

// ---------------------------------------------------------------------------
// Pass 1: y' = x @ W1a^T via ONE K=128 fp16 GEMM: A=[xh|xl], B=[wh|wh].
// 128 rows x 64 cols per CTA, 256 threads (8 warps x 16 rows).
// A tile: 128 rows x 256B (pairs 0..31 = xh, 32..63 = xl), pair p at p^((r&7)<<2).
// B tile: 16KB linear copy of pre-swizzled image.
// Fragment LDS conflict-free; mapping identical to validated R12 kernel.
// ---------------------------------------------------------------------------
__global__ __launch_bounds__(256) void k_pass1(const float* __restrict__ x,
                                               const void* __restrict__ o,
                                               int N, int B) {
    __shared__ __align__(16) unsigned char s_x[32768];
    __shared__ __align__(16) unsigned char s_w[16384];

    const int tid = threadIdx.x;
    const int wid = tid >> 5;
    const int l   = tid & 31;
    const int rowBase = blockIdx.x * TRB;

    int s0, e0, s1c;
    {
        int ob[MAXB];
        load_bounds(o, B, ob);
        s0 = seg_of(rowBase, ob);
        if (s0 > B - 1) s0 = B - 1;
        e0 = ob[s0];
        s1c = min(s0 + 1, B - 1);
    }

    // ---- W tile: linear copy ----
#pragma unroll
    for (int j = 0; j < 4; j++)
        ((uint4*)s_w)[tid + 256 * j] = ((const uint4*)g_w)[tid + 256 * j];

    // ---- x loader: fp16 hi/lo split into K-halves; x segment sums in regs ----
    const int lq = tid & 15;     // float4 index in row (k = 4lq..4lq+3)
    const int lr = tid >> 4;     // base row 0..15
    float sx0[4] = {0.f, 0.f, 0.f, 0.f};
    float sx1[4] = {0.f, 0.f, 0.f, 0.f};
#pragma unroll
    for (int j = 0; j < 8; j++) {
        int r = lr + 16 * j;
        int row = rowBase + r;
        float4 v = make_float4(0.f, 0.f, 0.f, 0.f);
        if (row < N) v = ((const float4*)x)[(size_t)row * 16 + lq];
        __half2 h01 = __floats2half2_rn(v.x, v.y);
        __half2 h23 = __floats2half2_rn(v.z, v.w);
        float2 hf01 = __half22float2(h01);
        float2 hf23 = __half22float2(h23);
        __half2 l01 = __floats2half2_rn(v.x - hf01.x, v.y - hf01.y);
        __half2 l23 = __floats2half2_rn(v.z - hf23.x, v.w - hf23.y);
        int sw = (r & 7) << 2;
        unsigned char* rb = s_x + r * 256;
        *(uint32_t*)(rb + (((2 * lq)      ) ^ sw) * 4) = h2_as_u32(h01);
        *(uint32_t*)(rb + (((2 * lq) + 1  ) ^ sw) * 4) = h2_as_u32(h23);
        *(uint32_t*)(rb + (((2 * lq) + 32 ) ^ sw) * 4) = h2_as_u32(l01);
        *(uint32_t*)(rb + (((2 * lq) + 33 ) ^ sw) * 4) = h2_as_u32(l23);
        if (row >= e0) { sx1[0]+=v.x; sx1[1]+=v.y; sx1[2]+=v.z; sx1[3]+=v.w; }
        else           { sx0[0]+=v.x; sx0[1]+=v.y; sx0[2]+=v.z; sx0[3]+=v.w; }
    }
#pragma unroll
    for (int m = 0; m < 4; m++) {
        sx0[m] += __shfl_xor_sync(0xffffffffu, sx0[m], 16);
        sx1[m] += __shfl_xor_sync(0xffffffffu, sx1[m], 16);
    }
    __syncthreads();

    // ---- GEMM: warp tile 16 rows x 64 cols, K=128 (8 k-steps) ----
    const int mb = wid * 16;
    const int qr = l >> 2;        // 0..7
    const int qc = l & 3;
    const int sw = qr << 2;

    float acc[8][4];
#pragma unroll
    for (int nt = 0; nt < 8; nt++)
#pragma unroll
        for (int e = 0; e < 4; e++) acc[nt][e] = 0.f;

#pragma unroll
    for (int kk = 0; kk < 8; kk++) {
        int pa0 = ((kk * 8 + qc) ^ sw) * 4;
        int pa2 = ((kk * 8 + 4 + qc) ^ sw) * 4;
        const unsigned char* rA0 = s_x + (mb + qr) * 256;
        const unsigned char* rA1 = s_x + (mb + qr + 8) * 256;
        uint32_t a0 = *(const uint32_t*)(rA0 + pa0);
        uint32_t a1 = *(const uint32_t*)(rA1 + pa0);
        uint32_t a2 = *(const uint32_t*)(rA0 + pa2);
        uint32_t a3 = *(const uint32_t*)(rA1 + pa2);
#pragma unroll
        for (int nt = 0; nt < 8; nt++) {
            const unsigned char* rB = s_w + (nt * 8 + qr) * 256;
            uint32_t b0 = *(const uint32_t*)(rB + pa0);
            uint32_t b1 = *(const uint32_t*)(rB + pa2);
            mma_f16(acc[nt], a0, a1, a2, a3, b0, b1);
        }
    }

    // ---- store y' ----
    {
        int row0 = rowBase + mb + qr;
        int row1 = row0 + 8;
#pragma unroll
        for (int nt = 0; nt < 8; nt++) {
            int col = nt * 8 + 2 * qc;
            if (row0 < N)
                *(float2*)&g_scratch[(size_t)row0 * CC + col] = make_float2(acc[nt][0], acc[nt][1]);
            if (row1 < N)
                *(float2*)&g_scratch[(size_t)row1 * CC + col] = make_float2(acc[nt][2], acc[nt][3]);
        }
    }

    // ---- y' stats ----
    float ss[8][2], qs[8][2];
#pragma unroll
    for (int nt = 0; nt < 8; nt++) {
        ss[nt][0] = acc[nt][0] + acc[nt][2];
        ss[nt][1] = acc[nt][1] + acc[nt][3];
        qs[nt][0] = acc[nt][0] * acc[nt][0] + acc[nt][2] * acc[nt][2];
        qs[nt][1] = acc[nt][1] * acc[nt][1] + acc[nt][3] * acc[nt][3];
    }
#pragma unroll
    for (int nt = 0; nt < 8; nt++)
#pragma unroll
        for (int e = 0; e < 2; e++) {
#pragma unroll
            for (int off = 4; off <= 16; off <<= 1) {
                ss[nt][e] += __shfl_xor_sync(0xffffffffu, ss[nt][e], off);
                qs[nt][e] += __shfl_xor_sync(0xffffffffu, qs[nt][e], off);
            }
        }

    __syncthreads();                       // all warps done reading s_w
    float* stg = (float*)s_w;              // [0:128) ssy, [128:192) ssq, [192:320) ssx
    if (tid < 320) stg[tid] = 0.f;
    __syncthreads();

    int slotY = ((rowBase + mb) >= e0) ? 1 : 0;   // boundary %16 == 0
    if (l < 4) {
#pragma unroll
        for (int nt = 0; nt < 8; nt++)
#pragma unroll
            for (int e = 0; e < 2; e++) {
                int col = nt * 8 + 2 * l + e;
                atomicAdd(&stg[slotY * 64 + col], ss[nt][e]);
                atomicAdd(&stg[128 + col], qs[nt][e]);
            }
    }
    if (l < 16) {
#pragma unroll
        for (int m = 0; m < 4; m++) {
            atomicAdd(&stg[192 + 4 * lq + m], sx0[m]);
            atomicAdd(&stg[256 + 4 * lq + m], sx1[m]);
        }
    }
    __syncthreads();

    if (tid < 64) {
        atomicAdd(&g_ssq[tid], stg[128 + tid]);
        atomicAdd(&g_ssy[s0 * CC + tid], stg[tid]);
        atomicAdd(&g_ssy[s1c * CC + tid], stg[64 + tid]);
        atomicAdd(&g_ssx[s0 * CC + tid], stg[192 + tid]);
        atomicAdd(&g_ssx[s1c * CC + tid], stg[256 + tid]);
    }
}

// ---------------------------------------------------------------------------
// Tiny kernel: means -> h -> c -> analytic BN stats -> folded (a, d)
// ---------------------------------------------------------------------------
__global__ void k_mid(const void* __restrict__ o,
                      const float* __restrict__ w2, const float* __restrict__ b2,
                      const float* __restrict__ w1, const float* __restrict__ b1,
                      const float* __restrict__ gm, const float* __restrict__ bt,
                      int N, int B) {
    __shared__ float sm[MAXB][CC];
    __shared__ float sh[MAXB][CC];
    __shared__ float scn[MAXB];
    int oc = threadIdx.x;

    int ob[MAXB];
    load_bounds(o, B, ob);
    if (oc < MAXB) {
        int prev = (oc == 0) ? 0 : ob[oc - 1];
        scn[oc] = (oc < B) ? (float)(ob[oc] - prev) : 1.f;
    }
    __syncthreads();
    for (int b = 0; b < B; b++) sm[b][oc] = g_ssx[b * CC + oc] / scn[b];
    __syncthreads();
    for (int b = 0; b < B; b++) {
        float s = b2[oc];
        for (int ic = 0; ic < CC; ic++) s += sm[b][ic] * w2[oc * CC + ic];
        sh[b][oc] = fmaxf(s, 0.f);
    }
    __syncthreads();

    float cv[MAXB];
    float sumy = 0.f, ey2 = g_ssq[oc];
    for (int b = 0; b < B; b++) {
        float s = b1[oc];
        for (int ic = 0; ic < CC; ic++) s += sh[b][ic] * w1[oc * 2 * CC + CC + ic];
        cv[b] = s;
        float sy = g_ssy[b * CC + oc];
        sumy += sy + scn[b] * s;
        ey2 += 2.f * s * sy + scn[b] * s * s;
    }
    float invN = 1.f / (float)N;
    float mu = sumy * invN;
    float var = ey2 * invN - mu * mu;
    float a = gm[oc] * rsqrtf(var + 1e-5f);
    g_a[oc] = a;
    for (int b = 0; b < B; b++) g_d[b * CC + oc] = (cv[b] - mu) * a + bt[oc];
}

// ---------------------------------------------------------------------------
// Pass 2: out = relu(y' * a[ch] + d[seg][ch])   (unchanged; at its roofline)
// ---------------------------------------------------------------------------
__global__ __launch_bounds__(256) void k_pass2(const void* __restrict__ o,
                                               float* __restrict__ out,
                                               int N, int B) {
    __shared__ float sa[CC];
    __shared__ float sd[MAXB * CC];
    __shared__ int so[MAXB];
    int tid = threadIdx.x;
    if (tid < CC) sa[tid] = g_a[tid];
    for (int i2 = tid; i2 < MAXB * CC; i2 += 256) sd[i2] = g_d[i2];
    if (tid < MAXB) {
        int ob[MAXB];
        load_bounds(o, B, ob);
        so[tid] = ob[tid];
    }
    __syncthreads();

    int total4 = N * (CC / 4);
    for (int i = blockIdx.x * 256 + tid; i < total4; i += gridDim.x * 256) {
        int row = i >> 4;
        int c4 = (i & 15) << 2;
        int sg = 0;
#pragma unroll
        for (int j = 0; j < MAXB; j++) sg += (row >= so[j]) ? 1 : 0;
        if (sg >= B) sg = B - 1;

        float4 v = *(const float4*)&g_scratch[(size_t)i * 4];
        const float* dp = &sd[sg * CC + c4];
        v.x = fmaxf(fmaf(v.x, sa[c4 + 0], dp[0]), 0.f);
        v.y = fmaxf(fmaf(v.y, sa[c4 + 1], dp[1]), 0.f);
        v.z = fmaxf(fmaf(v.z, sa[c4 + 2], dp[2]), 0.f);
        v.w = fmaxf(fmaf(v.w, sa[c4 + 3], dp[3]), 0.f);
        *(float4*)&out[(size_t)i * 4] = v;
    }
}

// ---------------------------------------------------------------------------
extern "C" void kernel_launch(void* const* d_in, const int* in_sizes, int n_in,
                              void* d_out, int out_size) {
    const float* x  = (const float*)d_in[0];
    const void*  o  = d_in[1];
    const float* w2 = (const float*)d_in[2];
    const float* b2 = (const float*)d_in[3];
    const float* w1 = (const float*)d_in[4];
    const float* b1 = (const float*)d_in[5];
    const float* gm = (const float*)d_in[6];
    const float* bt = (const float*)d_in[7];
    float* out = (float*)d_out;

    int N = in_sizes[0] / CC;
    int B = in_sizes[1];
    if (B > MAXB) B = MAXB;
    if (N > MAXN) N = MAXN;

    k_prep<<<16, 256>>>(w1);
    int nb = (N + TRB - 1) / TRB;
    k_pass1<<<nb, 256>>>(x, o, N, B);
    k_mid<<<1, CC>>>(o, w2, b2, w1, b1, gm, bt, N, B);
    k_pass2<<<4096, 256>>>(o, out, N, B);
}

// round 17
// speedup vs baseline: 1.4449x; 1.4449x over previous
#include <cuda_runtime.h>
#include <cuda_bf16.h>
#include <cuda_fp16.h>
#include <cstdint>

#define CC   64
#define TRB  128          // rows per block in pass1
#define MAXN 800000
#define MAXB 8

__device__ __align__(16) __half g_scratch[(size_t)MAXN * CC];   // y' in fp16 (halved traffic)
__device__ __align__(16) unsigned char g_wh[8192];    // W1a hi bf16, pre-swizzled [n][p^((n&7)<<2)]
__device__ __align__(16) unsigned char g_wl[8192];    // W1a lo bf16
__device__ float g_ssx[MAXB * CC];
__device__ float g_ssy[MAXB * CC];
__device__ float g_ssq[CC];
__device__ float g_a[CC];
__device__ float g_d[MAXB * CC];

// ---------------------------------------------------------------------------
__device__ __forceinline__ void load_bounds(const void* o, int B, int ob[MAXB]) {
    bool i64 = (((const int*)o)[1] == 0);
#pragma unroll
    for (int j = 0; j < MAXB; j++) {
        if (j < B) {
            long long v = i64 ? ((const long long*)o)[j] : (long long)((const int*)o)[j];
            ob[j] = (int)v;
        } else {
            ob[j] = 0x7fffffff;
        }
    }
}
__device__ __forceinline__ int seg_of(int row, const int ob[MAXB]) {
    int s = 0;
#pragma unroll
    for (int j = 0; j < MAXB; j++) s += (row >= ob[j]) ? 1 : 0;
    return s;
}

__device__ __forceinline__ void mma_bf16(float* c, uint32_t a0, uint32_t a1,
                                         uint32_t a2, uint32_t a3,
                                         uint32_t b0, uint32_t b1) {
    asm("mma.sync.aligned.m16n8k16.row.col.f32.bf16.bf16.f32 "
        "{%0,%1,%2,%3}, {%4,%5,%6,%7}, {%8,%9}, {%0,%1,%2,%3};"
        : "+f"(c[0]), "+f"(c[1]), "+f"(c[2]), "+f"(c[3])
        : "r"(a0), "r"(a1), "r"(a2), "r"(a3), "r"(b0), "r"(b1));
}

__device__ __forceinline__ uint32_t pack_bf16(__nv_bfloat16 lo, __nv_bfloat16 hi) {
    return ((uint32_t)__bfloat16_as_ushort(hi) << 16) | (uint32_t)__bfloat16_as_ushort(lo);
}

__device__ __forceinline__ uint32_t pack_h2(float a, float b) {
    __half2 h = __floats2half2_rn(a, b);
    return *(uint32_t*)&h;
}

// ---------------------------------------------------------------------------
// prep: W1a -> bf16 hi/lo, swizzled images; zero stats.
// Layout: row n = 128B (32 bf16-pairs); pair p stored at p ^ ((n&7)<<2).
// ---------------------------------------------------------------------------
__global__ void k_prep(const float* __restrict__ w1) {
    int t = blockIdx.x * blockDim.x + threadIdx.x;   // 0..4095
    int n = t >> 6, k = t & 63;
    float wv = w1[n * 2 * CC + k];
    __nv_bfloat16 hb = __float2bfloat16(wv);
    __nv_bfloat16 lb = __float2bfloat16(wv - __bfloat162float(hb));
    int p = k >> 1;
    int pp = p ^ ((n & 7) << 2);
    int off = n * 128 + pp * 4 + (k & 1) * 2;
    *(__nv_bfloat16*)(g_wh + off) = hb;
    *(__nv_bfloat16*)(g_wl + off) = lb;
    if (t < MAXB * CC) { g_ssx[t] = 0.f; g_ssy[t] = 0.f; }
    if (t < CC) g_ssq[t] = 0.f;
}

// ---------------------------------------------------------------------------
// Pass 1: y' = x @ W1a^T via bf16 hi/lo mma.sync, fused stats.  (R12 proven)
// 128 rows x 64 cols per CTA, 256 threads (8 warps x 16 rows).
// Only change: y' stored to scratch as fp16 (half2-packed uint stores).
// ---------------------------------------------------------------------------
__global__ __launch_bounds__(256) void k_pass1(const float* __restrict__ x,
                                               const void* __restrict__ o,
                                               int N, int B) {
    __shared__ __align__(16) unsigned char s_xh[16384];
    __shared__ __align__(16) unsigned char s_xl[16384];
    __shared__ __align__(16) unsigned char s_wh[8192];
    __shared__ __align__(16) unsigned char s_wl[8192];

    const int tid = threadIdx.x;
    const int wid = tid >> 5;
    const int l   = tid & 31;
    const int rowBase = blockIdx.x * TRB;

    int s0, e0, s1c;
    {
        int ob[MAXB];
        load_bounds(o, B, ob);
        s0 = seg_of(rowBase, ob);
        if (s0 > B - 1) s0 = B - 1;
        e0 = ob[s0];
        s1c = min(s0 + 1, B - 1);
    }

    // ---- W tiles: linear copies ----
#pragma unroll
    for (int j = 0; j < 2; j++) {
        ((uint4*)s_wh)[tid + 256 * j] = ((const uint4*)g_wh)[tid + 256 * j];
        ((uint4*)s_wl)[tid + 256 * j] = ((const uint4*)g_wl)[tid + 256 * j];
    }

    // ---- x loader: hi/lo bf16, swizzled; x segment sums kept in registers ----
    const int lq = tid & 15;     // float4 index in row (k = 4lq..4lq+3)
    const int lr = tid >> 4;     // base row 0..15
    float sx0[4] = {0.f, 0.f, 0.f, 0.f};
    float sx1[4] = {0.f, 0.f, 0.f, 0.f};
#pragma unroll
    for (int j = 0; j < 8; j++) {
        int r = lr + 16 * j;
        int row = rowBase + r;
        float4 v = make_float4(0.f, 0.f, 0.f, 0.f);
        if (row < N) v = ((const float4*)x)[(size_t)row * 16 + lq];
        __nv_bfloat16 h0 = __float2bfloat16(v.x), h1 = __float2bfloat16(v.y);
        __nv_bfloat16 h2 = __float2bfloat16(v.z), h3 = __float2bfloat16(v.w);
        __nv_bfloat16 l0 = __float2bfloat16(v.x - __bfloat162float(h0));
        __nv_bfloat16 l1 = __float2bfloat16(v.y - __bfloat162float(h1));
        __nv_bfloat16 l2 = __float2bfloat16(v.z - __bfloat162float(h2));
        __nv_bfloat16 l3 = __float2bfloat16(v.w - __bfloat162float(h3));
        int sw = (r & 7) << 2;
        int p0 = (2 * lq) ^ sw, p1 = (2 * lq + 1) ^ sw;
        *(uint32_t*)(s_xh + r * 128 + p0 * 4) = pack_bf16(h0, h1);
        *(uint32_t*)(s_xh + r * 128 + p1 * 4) = pack_bf16(h2, h3);
        *(uint32_t*)(s_xl + r * 128 + p0 * 4) = pack_bf16(l0, l1);
        *(uint32_t*)(s_xl + r * 128 + p1 * 4) = pack_bf16(l2, l3);
        if (row >= e0) { sx1[0]+=v.x; sx1[1]+=v.y; sx1[2]+=v.z; sx1[3]+=v.w; }
        else           { sx0[0]+=v.x; sx0[1]+=v.y; sx0[2]+=v.z; sx0[3]+=v.w; }
    }
#pragma unroll
    for (int m = 0; m < 4; m++) {
        sx0[m] += __shfl_xor_sync(0xffffffffu, sx0[m], 16);
        sx1[m] += __shfl_xor_sync(0xffffffffu, sx1[m], 16);
    }
    __syncthreads();

    // ---- GEMM: warp tile 16 rows x 64 cols, hi/lo mma ----
    const int mb = wid * 16;
    const int qr = l >> 2;        // 0..7
    const int qc = l & 3;
    const int sw = qr << 2;

    float acc[8][4];
#pragma unroll
    for (int nt = 0; nt < 8; nt++)
#pragma unroll
        for (int e = 0; e < 4; e++) acc[nt][e] = 0.f;

#pragma unroll
    for (int kk = 0; kk < 4; kk++) {
        int pa0 = ((kk * 8 + qc) ^ sw) * 4;
        int pa2 = ((kk * 8 + 4 + qc) ^ sw) * 4;
        const unsigned char* rA0 = s_xh + (mb + qr) * 128;
        const unsigned char* rA1 = s_xh + (mb + qr + 8) * 128;
        const unsigned char* rL0 = s_xl + (mb + qr) * 128;
        const unsigned char* rL1 = s_xl + (mb + qr + 8) * 128;
        uint32_t ah0 = *(const uint32_t*)(rA0 + pa0);
        uint32_t ah1 = *(const uint32_t*)(rA1 + pa0);
        uint32_t ah2 = *(const uint32_t*)(rA0 + pa2);
        uint32_t ah3 = *(const uint32_t*)(rA1 + pa2);
        uint32_t al0 = *(const uint32_t*)(rL0 + pa0);
        uint32_t al1 = *(const uint32_t*)(rL1 + pa0);
        uint32_t al2 = *(const uint32_t*)(rL0 + pa2);
        uint32_t al3 = *(const uint32_t*)(rL1 + pa2);
#pragma unroll
        for (int nt = 0; nt < 8; nt++) {
            const unsigned char* rB = s_wh + (nt * 8 + qr) * 128;
            const unsigned char* rBl = s_wl + (nt * 8 + qr) * 128;
            uint32_t bh0 = *(const uint32_t*)(rB + pa0);
            uint32_t bh1 = *(const uint32_t*)(rB + pa2);
            uint32_t bl0 = *(const uint32_t*)(rBl + pa0);
            uint32_t bl1 = *(const uint32_t*)(rBl + pa2);
            mma_bf16(acc[nt], ah0, ah1, ah2, ah3, bh0, bh1);
            mma_bf16(acc[nt], al0, al1, al2, al3, bh0, bh1);
            mma_bf16(acc[nt], ah0, ah1, ah2, ah3, bl0, bl1);
        }
    }

    // ---- store y' as fp16 (4B per fragment-row pair; 4 qc-lanes -> 16B runs) ----
    {
        int row0 = rowBase + mb + qr;
        int row1 = row0 + 8;
        unsigned char* sc = (unsigned char*)g_scratch;
#pragma unroll
        for (int nt = 0; nt < 8; nt++) {
            int col = nt * 8 + 2 * qc;
            if (row0 < N)
                *(uint32_t*)(sc + ((size_t)row0 * CC + col) * 2) = pack_h2(acc[nt][0], acc[nt][1]);
            if (row1 < N)
                *(uint32_t*)(sc + ((size_t)row1 * CC + col) * 2) = pack_h2(acc[nt][2], acc[nt][3]);
        }
    }

    // ---- y' stats: per-col sums over the warp's 16 rows ----
    float ss[8][2], qs[8][2];
#pragma unroll
    for (int nt = 0; nt < 8; nt++) {
        ss[nt][0] = acc[nt][0] + acc[nt][2];
        ss[nt][1] = acc[nt][1] + acc[nt][3];
        qs[nt][0] = acc[nt][0] * acc[nt][0] + acc[nt][2] * acc[nt][2];
        qs[nt][1] = acc[nt][1] * acc[nt][1] + acc[nt][3] * acc[nt][3];
    }
#pragma unroll
    for (int nt = 0; nt < 8; nt++)
#pragma unroll
        for (int e = 0; e < 2; e++) {
#pragma unroll
            for (int off = 4; off <= 16; off <<= 1) {
                ss[nt][e] += __shfl_xor_sync(0xffffffffu, ss[nt][e], off);
                qs[nt][e] += __shfl_xor_sync(0xffffffffu, qs[nt][e], off);
            }
        }

    __syncthreads();                       // all warps done reading s_wh/s_wl
    float* stg = (float*)s_wh;             // staging: [0:128) ssy, [128:192) ssq, [192:320) ssx
    if (tid < 320) stg[tid] = 0.f;
    __syncthreads();

    int slotY = ((rowBase + mb) >= e0) ? 1 : 0;   // boundary %16 == 0
    if (l < 4) {
#pragma unroll
        for (int nt = 0; nt < 8; nt++)
#pragma unroll
            for (int e = 0; e < 2; e++) {
                int col = nt * 8 + 2 * l + e;
                atomicAdd(&stg[slotY * 64 + col], ss[nt][e]);
                atomicAdd(&stg[128 + col], qs[nt][e]);
            }
    }
    if (l < 16) {
#pragma unroll
        for (int m = 0; m < 4; m++) {
            atomicAdd(&stg[192 + 4 * lq + m], sx0[m]);
            atomicAdd(&stg[256 + 4 * lq + m], sx1[m]);
        }
    }
    __syncthreads();

    if (tid < 64) {
        atomicAdd(&g_ssq[tid], stg[128 + tid]);
        atomicAdd(&g_ssy[s0 * CC + tid], stg[tid]);
        atomicAdd(&g_ssy[s1c * CC + tid], stg[64 + tid]);
        atomicAdd(&g_ssx[s0 * CC + tid], stg[192 + tid]);
        atomicAdd(&g_ssx[s1c * CC + tid], stg[256 + tid]);
    }
}

// ---------------------------------------------------------------------------
// Tiny kernel: means -> h -> c -> analytic BN stats -> folded (a, d)
// ---------------------------------------------------------------------------
__global__ void k_mid(const void* __restrict__ o,
                      const float* __restrict__ w2, const float* __restrict__ b2,
                      const float* __restrict__ w1, const float* __restrict__ b1,
                      const float* __restrict__ gm, const float* __restrict__ bt,
                      int N, int B) {
    __shared__ float sm[MAXB][CC];
    __shared__ float sh[MAXB][CC];
    __shared__ float scn[MAXB];
    int oc = threadIdx.x;

    int ob[MAXB];
    load_bounds(o, B, ob);
    if (oc < MAXB) {
        int prev = (oc == 0) ? 0 : ob[oc - 1];
        scn[oc] = (oc < B) ? (float)(ob[oc] - prev) : 1.f;
    }
    __syncthreads();
    for (int b = 0; b < B; b++) sm[b][oc] = g_ssx[b * CC + oc] / scn[b];
    __syncthreads();
    for (int b = 0; b < B; b++) {
        float s = b2[oc];
        for (int ic = 0; ic < CC; ic++) s += sm[b][ic] * w2[oc * CC + ic];
        sh[b][oc] = fmaxf(s, 0.f);
    }
    __syncthreads();

    float cv[MAXB];
    float sumy = 0.f, ey2 = g_ssq[oc];
    for (int b = 0; b < B; b++) {
        float s = b1[oc];
        for (int ic = 0; ic < CC; ic++) s += sh[b][ic] * w1[oc * 2 * CC + CC + ic];
        cv[b] = s;
        float sy = g_ssy[b * CC + oc];
        sumy += sy + scn[b] * s;
        ey2 += 2.f * s * sy + scn[b] * s * s;
    }
    float invN = 1.f / (float)N;
    float mu = sumy * invN;
    float var = ey2 * invN - mu * mu;
    float a = gm[oc] * rsqrtf(var + 1e-5f);
    g_a[oc] = a;
    for (int b = 0; b < B; b++) g_d[b * CC + oc] = (cv[b] - mu) * a + bt[oc];
}

// ---------------------------------------------------------------------------
// Pass 2: out = relu(y'_fp16 * a[ch] + d[seg][ch])
// Reads 8B (4 halfs) per lane (coalesced), writes float4 (coalesced).
// ---------------------------------------------------------------------------
__global__ __launch_bounds__(256) void k_pass2(const void* __restrict__ o,
                                               float* __restrict__ out,
                                               int N, int B) {
    __shared__ float sa[CC];
    __shared__ float sd[MAXB * CC];
    __shared__ int so[MAXB];
    int tid = threadIdx.x;
    if (tid < CC) sa[tid] = g_a[tid];
    for (int i2 = tid; i2 < MAXB * CC; i2 += 256) sd[i2] = g_d[i2];
    if (tid < MAXB) {
        int ob[MAXB];
        load_bounds(o, B, ob);
        so[tid] = ob[tid];
    }
    __syncthreads();

    const unsigned char* sc = (const unsigned char*)g_scratch;
    int total4 = N * (CC / 4);
    for (int i = blockIdx.x * 256 + tid; i < total4; i += gridDim.x * 256) {
        int row = i >> 4;
        int c4 = (i & 15) << 2;
        int sg = 0;
#pragma unroll
        for (int j = 0; j < MAXB; j++) sg += (row >= so[j]) ? 1 : 0;
        if (sg >= B) sg = B - 1;

        uint2 raw = *(const uint2*)(sc + (size_t)i * 8);
        float2 f0 = __half22float2(*(__half2*)&raw.x);
        float2 f1 = __half22float2(*(__half2*)&raw.y);
        const float* dp = &sd[sg * CC + c4];
        float4 v;
        v.x = fmaxf(fmaf(f0.x, sa[c4 + 0], dp[0]), 0.f);
        v.y = fmaxf(fmaf(f0.y, sa[c4 + 1], dp[1]), 0.f);
        v.z = fmaxf(fmaf(f1.x, sa[c4 + 2], dp[2]), 0.f);
        v.w = fmaxf(fmaf(f1.y, sa[c4 + 3], dp[3]), 0.f);
        *(float4*)&out[(size_t)i * 4] = v;
    }
}

// ---------------------------------------------------------------------------
extern "C" void kernel_launch(void* const* d_in, const int* in_sizes, int n_in,
                              void* d_out, int out_size) {
    const float* x  = (const float*)d_in[0];
    const void*  o  = d_in[1];
    const float* w2 = (const float*)d_in[2];
    const float* b2 = (const float*)d_in[3];
    const float* w1 = (const float*)d_in[4];
    const float* b1 = (const float*)d_in[5];
    const float* gm = (const float*)d_in[6];
    const float* bt = (const float*)d_in[7];
    float* out = (float*)d_out;

    int N = in_sizes[0] / CC;
    int B = in_sizes[1];
    if (B > MAXB) B = MAXB;
    if (N > MAXN) N = MAXN;

    k_prep<<<16, 256>>>(w1);
    int nb = (N + TRB - 1) / TRB;
    k_pass1<<<nb, 256>>>(x, o, N, B);
    k_mid<<<1, CC>>>(o, w2, b2, w1, b1, gm, bt, N, B);
    k_pass2<<<4096, 256>>>(o, out, N, B);
}